// round 12
// baseline (speedup 1.0000x reference)
#include <cuda_runtime.h>
#include <cuda_bf16.h>

// ----------------------------------------------------------------------------
// rlf_53446573032131: hypernetwork (R10)
//   K1 trunk L1 + build_lists, K2 trunk L2-L4 + count snapshot, K3 theta
//   K4 hyper: CTA = (map, 64 samples), 512 thr / 16 warps, 16 outputs/warp,
//      f32 smem activations (LDS.32 = 1 wf, vs R9's packed LDS.64 = 2 wf),
//      dynamic smem 72KB (3 CTAs/SM -> ~75% occ). L1-wavefront model:
//      ~335 wf/sample vs R9's ~530.
// ----------------------------------------------------------------------------

#define NMAPS 64
#define BSZ   8192
#define CAP   512

// theta_e (in=2, sz=[64,64,16]):
//   W1@0 [2][64] | b1@128 | W2@192 [64][64] | b2@4288 | W3@4352 [64][16] | b3@5376
// theta_f (in=32, sz=[128,128,8]):
//   W1@0 [32][128] | b1@4096 | W2@4224 [128][128] | b2@20608 | W3@20736 [128][8] | b3@21760
#define TE_SZ 5456
#define TF_SZ 21768
#define TE_PAIRS (TE_SZ / 2)
#define TF_PAIRS (TF_SZ / 2)
#define ALL_PAIRS (TE_PAIRS + TF_PAIRS)

#define HYPER_SMEM (18432 * 4)   // 72 KB dynamic

__device__ int   g_count[NMAPS] = {0};
__device__ int   g_cnt_snap[NMAPS];
__device__ int   g_list[NMAPS * CAP];
__device__ __align__(16) float g_a1[NMAPS * 256];
__device__ __align__(16) float g_z[NMAPS * 32];
__device__ __align__(16) float g_te[NMAPS * TE_SZ];
__device__ __align__(16) float g_tf[NMAPS * TF_SZ];

typedef unsigned long long u64;

__device__ __forceinline__ float leaky(float x) { return fmaxf(x, 0.2f * x); }

// ---- packed f32x2 helpers ----
__device__ __forceinline__ void ffma2(u64& d, u64 a, u64 b) {
    asm("fma.rn.f32x2 %0, %1, %2, %0;" : "+l"(d) : "l"(a), "l"(b));
}
__device__ __forceinline__ u64 add2(u64 a, u64 b) {
    u64 d; asm("add.rn.f32x2 %0, %1, %2;" : "=l"(d) : "l"(a), "l"(b)); return d;
}
__device__ __forceinline__ u64 pack2(float x) {
    u64 r; asm("mov.b64 %0, {%1, %1};" : "=l"(r) : "f"(x)); return r;
}
__device__ __forceinline__ float2 unpack2(u64 v) {
    float2 r; asm("mov.b64 {%0, %1}, %2;" : "=f"(r.x), "=f"(r.y) : "l"(v)); return r;
}

// ------------------------------------------------- trunk L1 + build_lists --
__global__ __launch_bounds__(256) void trunk1_kernel(
    const int*   __restrict__ indices,
    const float* __restrict__ maps,
    const float* __restrict__ fc1_w, const float* __restrict__ fc1_b)
{
    int ot = blockIdx.x, mg = blockIdx.y;
    int tid = threadIdx.x;

    if (mg == 16) {                       // ---- build lists (8 blocks) ----
        int t = ot * 256 + tid;
        #pragma unroll
        for (int s = t; s < BSZ; s += 2048) {
            int m = indices[s];
            int pos = atomicAdd(&g_count[m], 1);
            if (pos < CAP) g_list[m * CAP + pos] = s;
        }
        return;
    }

    __shared__ float ms[4 * 1024];
    __shared__ float red[8 * 32 * 4];

    for (int i = tid; i < 4096; i += 256) ms[i] = maps[mg * 4096 + i];
    __syncthreads();

    int ol = tid & 31, part = tid >> 5;
    int o = ot * 32 + ol;
    float a0 = 0.f, a1 = 0.f, a2 = 0.f, a3 = 0.f;
    int i0 = part * 128;
    #pragma unroll 4
    for (int i = i0; i < i0 + 128; i++) {
        float w = fc1_w[i * 256 + o];
        a0 += ms[i] * w;
        a1 += ms[1024 + i] * w;
        a2 += ms[2048 + i] * w;
        a3 += ms[3072 + i] * w;
    }
    *(float4*)(red + (part * 32 + ol) * 4) = make_float4(a0, a1, a2, a3);
    __syncthreads();

    if (tid < 128) {
        int o2 = tid >> 2, mm = tid & 3;
        float s = fc1_b[ot * 32 + o2];
        #pragma unroll
        for (int p = 0; p < 8; p++) s += red[p * 128 + tid];
        g_a1[(mg * 4 + mm) * 256 + ot * 32 + o2] = leaky(s);
    }
}

// --------------------------------------------- trunk L2-L4 + count snapshot --
__global__ __launch_bounds__(512) void trunk2_kernel(
    const float* __restrict__ fc2_w, const float* __restrict__ fc2_b,
    const float* __restrict__ fc3_w, const float* __restrict__ fc3_b,
    const float* __restrict__ bn_w,  const float* __restrict__ bn_b)
{
    int m = blockIdx.x, tid = threadIdx.x;
    __shared__ float a1[256];
    __shared__ float red[512];
    __shared__ float a2[128];
    __shared__ float a3[128];

    if (tid == 0) {
        int c = g_count[m];
        g_cnt_snap[m] = (c > CAP) ? CAP : c;
        g_count[m] = 0;
    }

    if (tid < 256) a1[tid] = g_a1[m * 256 + tid];
    __syncthreads();

    {   // L2: 256 -> 128
        int o = tid & 127, p = tid >> 7;
        float c0 = 0.f, c1 = 0.f, c2 = 0.f, c3 = 0.f;
        int i0 = p * 64;
        #pragma unroll
        for (int i = i0; i < i0 + 64; i += 4) {
            c0 += a1[i + 0] * fc2_w[(i + 0) * 128 + o];
            c1 += a1[i + 1] * fc2_w[(i + 1) * 128 + o];
            c2 += a1[i + 2] * fc2_w[(i + 2) * 128 + o];
            c3 += a1[i + 3] * fc2_w[(i + 3) * 128 + o];
        }
        red[p * 128 + o] = c0 + c1 + c2 + c3;
    }
    __syncthreads();
    if (tid < 128)
        a2[tid] = leaky(red[tid] + red[128 + tid] + red[256 + tid]
                        + red[384 + tid] + fc2_b[tid]);
    __syncthreads();

    {   // L3: 128 -> 128
        int o = tid & 127, p = tid >> 7;
        float c0 = 0.f, c1 = 0.f, c2 = 0.f, c3 = 0.f;
        int i0 = p * 32;
        #pragma unroll
        for (int i = i0; i < i0 + 32; i += 4) {
            c0 += a2[i + 0] * fc3_w[(i + 0) * 128 + o];
            c1 += a2[i + 1] * fc3_w[(i + 1) * 128 + o];
            c2 += a2[i + 2] * fc3_w[(i + 2) * 128 + o];
            c3 += a2[i + 3] * fc3_w[(i + 3) * 128 + o];
        }
        red[p * 128 + o] = c0 + c1 + c2 + c3;
    }
    __syncthreads();
    if (tid < 128)
        a3[tid] = leaky(red[tid] + red[128 + tid] + red[256 + tid]
                        + red[384 + tid] + fc3_b[tid]);
    __syncthreads();

    {   // L4 (bn): 128 -> 32
        int o = tid & 31, p = tid >> 5;
        float c = 0.f;
        #pragma unroll
        for (int i = p * 8; i < p * 8 + 8; i++)
            c += a3[i] * bn_w[i * 32 + o];
        red[p * 32 + o] = c;
    }
    __syncthreads();
    if (tid < 32) {
        float s = bn_b[tid];
        #pragma unroll
        for (int p = 0; p < 16; p++) s += red[p * 32 + tid];
        g_z[m * 32 + tid] = s;
    }
}

// ------------------------------------------------------------------- theta --
__global__ __launch_bounds__(128) void theta_kernel(
    const float* __restrict__ e_w, const float* __restrict__ e_b,
    const float* __restrict__ f_w, const float* __restrict__ f_b)
{
    __shared__ u64 szp[8 * 32];
    int tid = threadIdx.x;
    int m0 = blockIdx.y * 8;
    for (int i = tid; i < 8 * 32; i += 128) szp[i] = pack2(g_z[m0 * 32 + i]);
    __syncthreads();

    int jp = blockIdx.x * 128 + tid;
    const float* W; const float* Bv; float* dst; int ncol; int j;
    if (jp < TE_PAIRS) { W = e_w; Bv = e_b; dst = g_te; ncol = TE_SZ; j = 2 * jp; }
    else {
        int t = jp - TE_PAIRS;
        if (t >= TF_PAIRS) return;
        W = f_w; Bv = f_b; dst = g_tf; ncol = TF_SZ; j = 2 * t;
    }

    u64 w[32];
    #pragma unroll
    for (int k = 0; k < 32; k++) w[k] = *(const u64*)(W + k * ncol + j);
    u64 bb = *(const u64*)(Bv + j);

    #pragma unroll
    for (int mm = 0; mm < 8; mm++) {
        const ulonglong2* zp = (const ulonglong2*)(szp + mm * 32);
        u64 a0 = bb, a1 = 0, a2 = 0, a3 = 0;
        #pragma unroll
        for (int kk = 0; kk < 16; kk += 2) {
            ulonglong2 za = zp[kk], zb = zp[kk + 1];
            ffma2(a0, za.x, w[2 * kk + 0]); ffma2(a1, za.y, w[2 * kk + 1]);
            ffma2(a2, zb.x, w[2 * kk + 2]); ffma2(a3, zb.y, w[2 * kk + 3]);
        }
        *(u64*)(dst + (m0 + mm) * ncol + j) = add2(add2(a0, a1), add2(a2, a3));
    }
}

// -------------------------------------------------------------------- main --
// CTA = (map, 64 samples), 512 threads / 16 warps, dynamic smem 72KB.
// e-phase: 128 act-columns (2 streams x 2 groups x 32 lanes); warp w ->
//   colblock cb = w&3 (st = cb>>1, grp = cb&1), output-quarter oq = w>>2.
// f-phase: 64 sample-columns; warp w -> colblock fcb = w&1, outputs og=w>>1.
// Regions (f32): A[8192] = sE[64][128] / sF[128][64];
//                B[8192] = sB[64][128] / sAng[16][8][32];
//                C[2048] = sZ[32][64].
__global__ __launch_bounds__(512) void hyper_kernel(
    const float* __restrict__ states, float* __restrict__ out)
{
    extern __shared__ float SMF[];
    float* A = SMF;
    float* Bm = SMF + 8192;
    float* C = SMF + 16384;

    int m = blockIdx.x;
    int cnt = g_cnt_snap[m];
    int base = blockIdx.y * 64;
    if (base >= cnt) return;

    int tid  = threadIdx.x;
    int lane = tid & 31;
    int w    = tid >> 5;        // 0..15

    const float* te = g_te + m * TE_SZ;
    const float* tf = g_tf + m * TF_SZ;

    // ---------------- e-phase mapping ----------------
    int cb  = w & 3;            // colblock 0..3
    int oq  = w >> 2;           // output quarter 0..3
    int est = cb >> 1;          // stream: 0=S, 1=G
    int eg  = cb & 1;           // sample group
    int ecol = cb * 32 + lane;  // 0..127
    int esidx = base + eg * 32 + lane;
    bool evalid = esidx < cnt;
    int eb = g_list[m * CAP + (evalid ? esidx : base)];
    float2 xv = *(const float2*)(states + 4 * eb + est * 2);

    // ---- e1: 2 -> 64 (leaky), out A[64][128] ----
    {
        int jq = oq * 16;
        #pragma unroll
        for (int j0 = 0; j0 < 16; j0 += 4) {
            int j = jq + j0;
            float4 w0 = *(const float4*)(te + j);
            float4 w1 = *(const float4*)(te + 64 + j);
            float4 bb = *(const float4*)(te + 128 + j);
            A[(j + 0) * 128 + ecol] = leaky(fmaf(xv.x, w0.x, fmaf(xv.y, w1.x, bb.x)));
            A[(j + 1) * 128 + ecol] = leaky(fmaf(xv.x, w0.y, fmaf(xv.y, w1.y, bb.y)));
            A[(j + 2) * 128 + ecol] = leaky(fmaf(xv.x, w0.z, fmaf(xv.y, w1.z, bb.z)));
            A[(j + 3) * 128 + ecol] = leaky(fmaf(xv.x, w0.w, fmaf(xv.y, w1.w, bb.w)));
        }
    }
    __syncthreads();

    // ---- e2: 64 -> 64 (leaky), A -> Bm, 16 outputs/warp ----
    {
        int jh = oq * 16;
        u64 acc[8];
        {
            const ulonglong2* bp = (const ulonglong2*)(te + 4288 + jh);
            #pragma unroll
            for (int t = 0; t < 4; t++) { ulonglong2 v = bp[t]; acc[2*t] = v.x; acc[2*t+1] = v.y; }
        }
        #pragma unroll 2
        for (int k = 0; k < 64; k++) {
            u64 hh = pack2(A[k * 128 + ecol]);
            const ulonglong2* wp = (const ulonglong2*)(te + 192 + k * 64 + jh);
            #pragma unroll
            for (int t = 0; t < 4; t++) {
                ulonglong2 wv = wp[t];
                ffma2(acc[2*t], hh, wv.x); ffma2(acc[2*t+1], hh, wv.y);
            }
        }
        __syncthreads();          // all e2 reads of A done before Bm?? (Bm != A: not needed for A; but keep barrier AFTER writes instead)
        #pragma unroll
        for (int t = 0; t < 8; t++) {
            float2 r = unpack2(acc[t]);
            Bm[(jh + 2*t + 0) * 128 + ecol] = leaky(r.x);
            Bm[(jh + 2*t + 1) * 128 + ecol] = leaky(r.y);
        }
    }
    __syncthreads();

    // ---- e3: 64 -> 16 (no act), Bm -> C (zf [32][64]) ----
    {
        int j3 = oq * 4;
        ulonglong2 bb = *(const ulonglong2*)(te + 5376 + j3);
        u64 a0 = bb.x, a1 = bb.y;
        #pragma unroll 4
        for (int k = 0; k < 64; k++) {
            u64 hh = pack2(Bm[k * 128 + ecol]);
            ulonglong2 wv = *(const ulonglong2*)(te + 4352 + k * 16 + j3);
            ffma2(a0, hh, wv.x); ffma2(a1, hh, wv.y);
        }
        int f = est * 16 + j3;
        int scol = eg * 32 + lane;
        float2 r;
        r = unpack2(a0); C[(f + 0) * 64 + scol] = r.x; C[(f + 1) * 64 + scol] = r.y;
        r = unpack2(a1); C[(f + 2) * 64 + scol] = r.x; C[(f + 3) * 64 + scol] = r.y;
    }
    __syncthreads();

    // ---------------- f-phase mapping ----------------
    int fcb = w & 1;
    int og  = w >> 1;
    int jf  = og * 16;
    int fcol = fcb * 32 + lane;

    // ---- f1: 32 -> 128 (leaky), C -> A (sF [128][64]) ----
    {
        u64 acc[8];
        {
            const ulonglong2* bp = (const ulonglong2*)(tf + 4096 + jf);
            #pragma unroll
            for (int t = 0; t < 4; t++) { ulonglong2 v = bp[t]; acc[2*t] = v.x; acc[2*t+1] = v.y; }
        }
        #pragma unroll 2
        for (int k = 0; k < 32; k++) {
            u64 hh = pack2(C[k * 64 + fcol]);
            const ulonglong2* wp = (const ulonglong2*)(tf + k * 128 + jf);
            #pragma unroll
            for (int t = 0; t < 4; t++) {
                ulonglong2 wv = wp[t];
                ffma2(acc[2*t], hh, wv.x); ffma2(acc[2*t+1], hh, wv.y);
            }
        }
        __syncthreads();          // everyone done reading A (e2) before overwrite
        #pragma unroll
        for (int t = 0; t < 8; t++) {
            float2 r = unpack2(acc[t]);
            A[(jf + 2*t + 0) * 64 + fcol] = leaky(r.x);
            A[(jf + 2*t + 1) * 64 + fcol] = leaky(r.y);
        }
    }
    __syncthreads();

    // ---- f2: 128 -> 128 (leaky), h2 in regs ----
    float h2[16];
    {
        u64 acc[8];
        {
            const ulonglong2* bp = (const ulonglong2*)(tf + 20608 + jf);
            #pragma unroll
            for (int t = 0; t < 4; t++) { ulonglong2 v = bp[t]; acc[2*t] = v.x; acc[2*t+1] = v.y; }
        }
        #pragma unroll 2
        for (int k = 0; k < 128; k++) {
            u64 hh = pack2(A[k * 64 + fcol]);
            const ulonglong2* wp = (const ulonglong2*)(tf + 4224 + k * 128 + jf);
            #pragma unroll
            for (int t = 0; t < 4; t++) {
                ulonglong2 wv = wp[t];
                ffma2(acc[2*t], hh, wv.x); ffma2(acc[2*t+1], hh, wv.y);
            }
        }
        #pragma unroll
        for (int t = 0; t < 8; t++) {
            float2 r = unpack2(acc[t]);
            h2[2*t]     = leaky(r.x);
            h2[2*t + 1] = leaky(r.y);
        }
    }

    // ---- f3 partials from regs -> sAng (overlays Bm; last read was e3) ----
    {
        u64 g0 = 0, g1 = 0, g2 = 0, g3 = 0;
        #pragma unroll 4
        for (int t = 0; t < 16; t++) {
            u64 hh = pack2(h2[t]);
            const ulonglong2* wp = (const ulonglong2*)(tf + 20736 + (jf + t) * 8);
            ulonglong2 wa = wp[0], wb = wp[1];
            ffma2(g0, hh, wa.x); ffma2(g1, hh, wa.y);
            ffma2(g2, hh, wb.x); ffma2(g3, hh, wb.y);
        }
        float2 r;
        int bs = (og * 2 + fcb) * 8;
        r = unpack2(g0); Bm[(bs + 0) * 32 + lane] = r.x; Bm[(bs + 1) * 32 + lane] = r.y;
        r = unpack2(g1); Bm[(bs + 2) * 32 + lane] = r.x; Bm[(bs + 3) * 32 + lane] = r.y;
        r = unpack2(g2); Bm[(bs + 4) * 32 + lane] = r.x; Bm[(bs + 5) * 32 + lane] = r.y;
        r = unpack2(g3); Bm[(bs + 6) * 32 + lane] = r.x; Bm[(bs + 7) * 32 + lane] = r.y;
    }
    __syncthreads();

    // ---- reduce 8 og-partials; warp w -> (angle r = w>>1, colblock w&1) ----
    {
        int r  = w >> 1;
        int fc = w & 1;
        int sidx2 = base + fc * 32 + lane;
        if (sidx2 < cnt) {
            int b2 = g_list[m * CAP + sidx2];
            float s = tf[21760 + r];
            #pragma unroll
            for (int o2 = 0; o2 < 8; o2++)
                s += Bm[((o2 * 2 + fc) * 8 + r) * 32 + lane];
            out[b2 * 16 + r]     = __sinf(s);
            out[b2 * 16 + 8 + r] = __cosf(s);
        }
    }
}

// ----------------------------------------------------------------- launch --
extern "C" void kernel_launch(void* const* d_in, const int* in_sizes, int n_in,
                              void* d_out, int out_size)
{
    const int*   indices = (const int*)  d_in[0];
    const float* states  = (const float*)d_in[1];
    const float* maps    = (const float*)d_in[2];
    const float* fc1_w   = (const float*)d_in[3];
    const float* fc1_b   = (const float*)d_in[4];
    const float* fc2_w   = (const float*)d_in[5];
    const float* fc2_b   = (const float*)d_in[6];
    const float* fc3_w   = (const float*)d_in[7];
    const float* fc3_b   = (const float*)d_in[8];
    const float* bn_w    = (const float*)d_in[9];
    const float* bn_b    = (const float*)d_in[10];
    const float* e_w     = (const float*)d_in[11];
    const float* e_b     = (const float*)d_in[12];
    const float* f_w     = (const float*)d_in[13];
    const float* f_b     = (const float*)d_in[14];
    float* out = (float*)d_out;

    cudaFuncSetAttribute(hyper_kernel,
                         cudaFuncAttributeMaxDynamicSharedMemorySize, HYPER_SMEM);

    trunk1_kernel<<<dim3(8, 17), 256>>>(indices, maps, fc1_w, fc1_b);
    trunk2_kernel<<<NMAPS, 512>>>(fc2_w, fc2_b, fc3_w, fc3_b, bn_w, bn_b);
    theta_kernel<<<dim3((ALL_PAIRS + 127) / 128, 8), 128>>>(e_w, e_b, f_w, f_b);
    hyper_kernel<<<dim3(NMAPS, CAP / 64), 512, HYPER_SMEM>>>(states, out);
}

// round 14
// speedup vs baseline: 1.4843x; 1.4843x over previous
#include <cuda_runtime.h>
#include <cuda_bf16.h>

// ----------------------------------------------------------------------------
// rlf_53446573032131: hypernetwork (R12 = R9 revert + f32 f-phase smem)
//   R10's 16-output/warp restructure spilled (regs 44->64, 2.3x issued slots,
//   162us). This is the R9 shape (32 samples/CTA, 512thr/16 warps, 8 outputs
//   per warp, acc[4]) with ONE change: f-phase activations stored f32 in smem
//   (LDS.32 = 1 wavefront) and packed to u64 in registers, instead of R9's
//   packed-u64 smem (LDS.64 = 2 wavefronts). Halves LDS wf in f1/f2.
// ----------------------------------------------------------------------------

#define NMAPS 64
#define BSZ   8192
#define CAP   512

// theta_e (in=2, sz=[64,64,16]):
//   W1@0 [2][64] | b1@128 | W2@192 [64][64] | b2@4288 | W3@4352 [64][16] | b3@5376
// theta_f (in=32, sz=[128,128,8]):
//   W1@0 [32][128] | b1@4096 | W2@4224 [128][128] | b2@20608 | W3@20736 [128][8] | b3@21760
#define TE_SZ 5456
#define TF_SZ 21768
#define TE_PAIRS (TE_SZ / 2)
#define TF_PAIRS (TF_SZ / 2)
#define ALL_PAIRS (TE_PAIRS + TF_PAIRS)

__device__ int   g_count[NMAPS] = {0};
__device__ int   g_cnt_snap[NMAPS];
__device__ int   g_list[NMAPS * CAP];
__device__ __align__(16) float g_a1[NMAPS * 256];
__device__ __align__(16) float g_z[NMAPS * 32];
__device__ __align__(16) float g_te[NMAPS * TE_SZ];
__device__ __align__(16) float g_tf[NMAPS * TF_SZ];

typedef unsigned long long u64;

__device__ __forceinline__ float leaky(float x) { return fmaxf(x, 0.2f * x); }

// ---- packed f32x2 helpers ----
__device__ __forceinline__ void ffma2(u64& d, u64 a, u64 b) {
    asm("fma.rn.f32x2 %0, %1, %2, %0;" : "+l"(d) : "l"(a), "l"(b));
}
__device__ __forceinline__ u64 add2(u64 a, u64 b) {
    u64 d; asm("add.rn.f32x2 %0, %1, %2;" : "=l"(d) : "l"(a), "l"(b)); return d;
}
__device__ __forceinline__ u64 pack2(float x) {
    u64 r; asm("mov.b64 %0, {%1, %1};" : "=l"(r) : "f"(x)); return r;
}
__device__ __forceinline__ float2 unpack2(u64 v) {
    float2 r; asm("mov.b64 {%0, %1}, %2;" : "=f"(r.x), "=f"(r.y) : "l"(v)); return r;
}

// ------------------------------------------------- trunk L1 + build_lists --
__global__ __launch_bounds__(256) void trunk1_kernel(
    const int*   __restrict__ indices,
    const float* __restrict__ maps,
    const float* __restrict__ fc1_w, const float* __restrict__ fc1_b)
{
    int ot = blockIdx.x, mg = blockIdx.y;
    int tid = threadIdx.x;

    if (mg == 16) {                       // ---- build lists (8 blocks) ----
        int t = ot * 256 + tid;
        #pragma unroll
        for (int s = t; s < BSZ; s += 2048) {
            int m = indices[s];
            int pos = atomicAdd(&g_count[m], 1);
            if (pos < CAP) g_list[m * CAP + pos] = s;
        }
        return;
    }

    __shared__ float ms[4 * 1024];
    __shared__ float red[8 * 32 * 4];

    for (int i = tid; i < 4096; i += 256) ms[i] = maps[mg * 4096 + i];
    __syncthreads();

    int ol = tid & 31, part = tid >> 5;
    int o = ot * 32 + ol;
    float a0 = 0.f, a1 = 0.f, a2 = 0.f, a3 = 0.f;
    int i0 = part * 128;
    #pragma unroll 4
    for (int i = i0; i < i0 + 128; i++) {
        float w = fc1_w[i * 256 + o];
        a0 += ms[i] * w;
        a1 += ms[1024 + i] * w;
        a2 += ms[2048 + i] * w;
        a3 += ms[3072 + i] * w;
    }
    *(float4*)(red + (part * 32 + ol) * 4) = make_float4(a0, a1, a2, a3);
    __syncthreads();

    if (tid < 128) {
        int o2 = tid >> 2, mm = tid & 3;
        float s = fc1_b[ot * 32 + o2];
        #pragma unroll
        for (int p = 0; p < 8; p++) s += red[p * 128 + tid];
        g_a1[(mg * 4 + mm) * 256 + ot * 32 + o2] = leaky(s);
    }
}

// --------------------------------------------- trunk L2-L4 + count snapshot --
__global__ __launch_bounds__(512) void trunk2_kernel(
    const float* __restrict__ fc2_w, const float* __restrict__ fc2_b,
    const float* __restrict__ fc3_w, const float* __restrict__ fc3_b,
    const float* __restrict__ bn_w,  const float* __restrict__ bn_b)
{
    int m = blockIdx.x, tid = threadIdx.x;
    __shared__ float a1[256];
    __shared__ float red[512];
    __shared__ float a2[128];
    __shared__ float a3[128];

    if (tid == 0) {
        int c = g_count[m];
        g_cnt_snap[m] = (c > CAP) ? CAP : c;
        g_count[m] = 0;
    }

    if (tid < 256) a1[tid] = g_a1[m * 256 + tid];
    __syncthreads();

    {   // L2: 256 -> 128
        int o = tid & 127, p = tid >> 7;
        float c0 = 0.f, c1 = 0.f, c2 = 0.f, c3 = 0.f;
        int i0 = p * 64;
        #pragma unroll
        for (int i = i0; i < i0 + 64; i += 4) {
            c0 += a1[i + 0] * fc2_w[(i + 0) * 128 + o];
            c1 += a1[i + 1] * fc2_w[(i + 1) * 128 + o];
            c2 += a1[i + 2] * fc2_w[(i + 2) * 128 + o];
            c3 += a1[i + 3] * fc2_w[(i + 3) * 128 + o];
        }
        red[p * 128 + o] = c0 + c1 + c2 + c3;
    }
    __syncthreads();
    if (tid < 128)
        a2[tid] = leaky(red[tid] + red[128 + tid] + red[256 + tid]
                        + red[384 + tid] + fc2_b[tid]);
    __syncthreads();

    {   // L3: 128 -> 128
        int o = tid & 127, p = tid >> 7;
        float c0 = 0.f, c1 = 0.f, c2 = 0.f, c3 = 0.f;
        int i0 = p * 32;
        #pragma unroll
        for (int i = i0; i < i0 + 32; i += 4) {
            c0 += a2[i + 0] * fc3_w[(i + 0) * 128 + o];
            c1 += a2[i + 1] * fc3_w[(i + 1) * 128 + o];
            c2 += a2[i + 2] * fc3_w[(i + 2) * 128 + o];
            c3 += a2[i + 3] * fc3_w[(i + 3) * 128 + o];
        }
        red[p * 128 + o] = c0 + c1 + c2 + c3;
    }
    __syncthreads();
    if (tid < 128)
        a3[tid] = leaky(red[tid] + red[128 + tid] + red[256 + tid]
                        + red[384 + tid] + fc3_b[tid]);
    __syncthreads();

    {   // L4 (bn): 128 -> 32
        int o = tid & 31, p = tid >> 5;
        float c = 0.f;
        #pragma unroll
        for (int i = p * 8; i < p * 8 + 8; i++)
            c += a3[i] * bn_w[i * 32 + o];
        red[p * 32 + o] = c;
    }
    __syncthreads();
    if (tid < 32) {
        float s = bn_b[tid];
        #pragma unroll
        for (int p = 0; p < 16; p++) s += red[p * 32 + tid];
        g_z[m * 32 + tid] = s;
    }
}

// ------------------------------------------------------------------- theta --
__global__ __launch_bounds__(128) void theta_kernel(
    const float* __restrict__ e_w, const float* __restrict__ e_b,
    const float* __restrict__ f_w, const float* __restrict__ f_b)
{
    __shared__ u64 szp[8 * 32];
    int tid = threadIdx.x;
    int m0 = blockIdx.y * 8;
    for (int i = tid; i < 8 * 32; i += 128) szp[i] = pack2(g_z[m0 * 32 + i]);
    __syncthreads();

    int jp = blockIdx.x * 128 + tid;
    const float* W; const float* Bv; float* dst; int ncol; int j;
    if (jp < TE_PAIRS) { W = e_w; Bv = e_b; dst = g_te; ncol = TE_SZ; j = 2 * jp; }
    else {
        int t = jp - TE_PAIRS;
        if (t >= TF_PAIRS) return;
        W = f_w; Bv = f_b; dst = g_tf; ncol = TF_SZ; j = 2 * t;
    }

    u64 w[32];
    #pragma unroll
    for (int k = 0; k < 32; k++) w[k] = *(const u64*)(W + k * ncol + j);
    u64 bb = *(const u64*)(Bv + j);

    #pragma unroll
    for (int mm = 0; mm < 8; mm++) {
        const ulonglong2* zp = (const ulonglong2*)(szp + mm * 32);
        u64 a0 = bb, a1 = 0, a2 = 0, a3 = 0;
        #pragma unroll
        for (int kk = 0; kk < 16; kk += 2) {
            ulonglong2 za = zp[kk], zb = zp[kk + 1];
            ffma2(a0, za.x, w[2 * kk + 0]); ffma2(a1, za.y, w[2 * kk + 1]);
            ffma2(a2, zb.x, w[2 * kk + 2]); ffma2(a3, zb.y, w[2 * kk + 3]);
        }
        *(u64*)(dst + (m0 + mm) * ncol + j) = add2(add2(a0, a1), add2(a2, a3));
    }
}

// -------------------------------------------------------------------- main --
// CTA = (map, 32 samples), 512 threads / 16 warps (R9 shape: regs ~44,
// occ ~45%). All smem activations f32; pack2 in registers.
// smem: X 32KB float[8192]:
//   e-phase: sE = X[0:4096] [64][64], sB = X[4096:8192] [64][64]
//   f-phase: sF = X[0:4096] [128][32] (overlays sE; e-reads done)
//   tail:    h2s = X[0:4096] (overlays sF after sync)
// sZ 4KB float[32][32].  Total 36KB static.
__global__ __launch_bounds__(512) void hyper_kernel(
    const float* __restrict__ states, float* __restrict__ out)
{
    int m = blockIdx.x;
    int cnt = g_cnt_snap[m];
    int base = blockIdx.y * 32;
    if (base >= cnt) return;

    int tid  = threadIdx.x;
    int lane = tid & 31;
    int w    = tid >> 5;        // 0..15
    int st   = w >> 3;          // e-stream: 0 = S, 1 = G
    int wq   = w & 7;           // warp-in-stream
    int sidx = base + lane;
    bool valid = sidx < cnt;
    int b = g_list[m * CAP + (valid ? sidx : base)];

    const float* te = g_te + m * TE_SZ;
    const float* tf = g_tf + m * TF_SZ;

    __shared__ __align__(16) float X[8192];   // 32KB multi-purpose
    __shared__ __align__(16) float sZ[1024];  // zf [32][32]

    float* sE  = X;           // [64][64] e1 out
    float* sB  = X + 4096;    // [64][64] e2 out
    float* sF  = X;           // [128][32] f1 out
    float* h2s = X;           // [128][32] f2 out

    int col = lane + st * 32;
    float2 xv = *(const float2*)(states + 4 * b + st * 2);
    int jh = wq * 8;

    // ---- e1: 2 -> 64 (leaky) ----
    #pragma unroll
    for (int j0 = 0; j0 < 8; j0 += 4) {
        int j = jh + j0;
        float4 w0 = *(const float4*)(te + j);
        float4 w1 = *(const float4*)(te + 64 + j);
        float4 bb = *(const float4*)(te + 128 + j);
        sE[(j + 0) * 64 + col] = leaky(fmaf(xv.x, w0.x, fmaf(xv.y, w1.x, bb.x)));
        sE[(j + 1) * 64 + col] = leaky(fmaf(xv.x, w0.y, fmaf(xv.y, w1.y, bb.y)));
        sE[(j + 2) * 64 + col] = leaky(fmaf(xv.x, w0.z, fmaf(xv.y, w1.z, bb.z)));
        sE[(j + 3) * 64 + col] = leaky(fmaf(xv.x, w0.w, fmaf(xv.y, w1.w, bb.w)));
    }
    __syncthreads();

    // ---- e2: 64 -> 64 (leaky), sE -> sB, 8 outputs/warp ----
    {
        u64 acc[4];
        {
            const ulonglong2* bp = (const ulonglong2*)(te + 4288 + jh);
            ulonglong2 v0 = bp[0], v1 = bp[1];
            acc[0] = v0.x; acc[1] = v0.y; acc[2] = v1.x; acc[3] = v1.y;
        }
        #pragma unroll 4
        for (int k = 0; k < 64; k++) {
            u64 hh = pack2(sE[k * 64 + col]);
            const ulonglong2* wp = (const ulonglong2*)(te + 192 + k * 64 + jh);
            ulonglong2 w0 = wp[0], w1 = wp[1];
            ffma2(acc[0], hh, w0.x); ffma2(acc[1], hh, w0.y);
            ffma2(acc[2], hh, w1.x); ffma2(acc[3], hh, w1.y);
        }
        #pragma unroll
        for (int t = 0; t < 4; t++) {
            float2 r = unpack2(acc[t]);
            sB[(jh + 2*t + 0) * 64 + col] = leaky(r.x);
            sB[(jh + 2*t + 1) * 64 + col] = leaky(r.y);
        }
    }
    __syncthreads();

    // ---- e3: 64 -> 16 (no act), sB -> sZ, 2 outputs/warp ----
    {
        int j = wq * 2;
        u64 a0 = *(const u64*)(te + 5376 + j);
        u64 a1 = 0;
        #pragma unroll 8
        for (int k = 0; k < 64; k += 2) {
            u64 h0 = pack2(sB[k * 64 + col]);
            u64 h1 = pack2(sB[(k + 1) * 64 + col]);
            u64 w0 = *(const u64*)(te + 4352 + k * 16 + j);
            u64 w1 = *(const u64*)(te + 4352 + (k + 1) * 16 + j);
            ffma2(a0, h0, w0); ffma2(a1, h1, w1);
        }
        float2 r = unpack2(add2(a0, a1));
        int f = j + st * 16;     // e_s -> zf[0:16], e_g -> zf[16:32]
        sZ[(f + 0) * 32 + lane] = r.x;
        sZ[(f + 1) * 32 + lane] = r.y;
    }
    __syncthreads();

    // ---- f1: 32 -> 128 (leaky), sZ -> sF, 8 outputs/warp ----
    int jf = w * 8;
    {
        u64 acc[4];
        {
            const ulonglong2* bp = (const ulonglong2*)(tf + 4096 + jf);
            ulonglong2 v0 = bp[0], v1 = bp[1];
            acc[0] = v0.x; acc[1] = v0.y; acc[2] = v1.x; acc[3] = v1.y;
        }
        #pragma unroll 4
        for (int k = 0; k < 32; k++) {
            u64 hh = pack2(sZ[k * 32 + lane]);
            const ulonglong2* wp = (const ulonglong2*)(tf + k * 128 + jf);
            ulonglong2 w0 = wp[0], w1 = wp[1];
            ffma2(acc[0], hh, w0.x); ffma2(acc[1], hh, w0.y);
            ffma2(acc[2], hh, w1.x); ffma2(acc[3], hh, w1.y);
        }
        // sF overlays sE; last sE/sB reads ended at the previous barrier.
        #pragma unroll
        for (int t = 0; t < 4; t++) {
            float2 r = unpack2(acc[t]);
            sF[(jf + 2*t + 0) * 32 + lane] = leaky(r.x);
            sF[(jf + 2*t + 1) * 32 + lane] = leaky(r.y);
        }
    }
    __syncthreads();

    // ---- f2: 128 -> 128 (leaky), 8 outputs/warp, h2 kept in regs ----
    float h2[8];
    {
        u64 acc[4];
        {
            const ulonglong2* bp = (const ulonglong2*)(tf + 20608 + jf);
            ulonglong2 v0 = bp[0], v1 = bp[1];
            acc[0] = v0.x; acc[1] = v0.y; acc[2] = v1.x; acc[3] = v1.y;
        }
        #pragma unroll 4
        for (int k = 0; k < 128; k++) {
            u64 hh = pack2(sF[k * 32 + lane]);
            const ulonglong2* wp = (const ulonglong2*)(tf + 4224 + k * 128 + jf);
            ulonglong2 w0 = wp[0], w1 = wp[1];
            ffma2(acc[0], hh, w0.x); ffma2(acc[1], hh, w0.y);
            ffma2(acc[2], hh, w1.x); ffma2(acc[3], hh, w1.y);
        }
        #pragma unroll
        for (int t = 0; t < 4; t++) {
            float2 r = unpack2(acc[t]);
            h2[2*t]     = leaky(r.x);
            h2[2*t + 1] = leaky(r.y);
        }
    }
    __syncthreads();            // everyone done READING sF
    #pragma unroll
    for (int t = 0; t < 8; t++) h2s[(jf + t) * 32 + lane] = h2[t];
    __syncthreads();

    // ---- f3: 128 -> 8, warp r (<8) computes angle r; sin/cos epilogue ----
    if (w < 8 && valid) {
        int r = w;
        float s = tf[21760 + r];
        #pragma unroll 8
        for (int j = 0; j < 128; j++)
            s = fmaf(h2s[j * 32 + lane], tf[20736 + j * 8 + r], s);
        out[b * 16 + r]     = __sinf(s);
        out[b * 16 + 8 + r] = __cosf(s);
    }
}

// ----------------------------------------------------------------- launch --
extern "C" void kernel_launch(void* const* d_in, const int* in_sizes, int n_in,
                              void* d_out, int out_size)
{
    const int*   indices = (const int*)  d_in[0];
    const float* states  = (const float*)d_in[1];
    const float* maps    = (const float*)d_in[2];
    const float* fc1_w   = (const float*)d_in[3];
    const float* fc1_b   = (const float*)d_in[4];
    const float* fc2_w   = (const float*)d_in[5];
    const float* fc2_b   = (const float*)d_in[6];
    const float* fc3_w   = (const float*)d_in[7];
    const float* fc3_b   = (const float*)d_in[8];
    const float* bn_w    = (const float*)d_in[9];
    const float* bn_b    = (const float*)d_in[10];
    const float* e_w     = (const float*)d_in[11];
    const float* e_b     = (const float*)d_in[12];
    const float* f_w     = (const float*)d_in[13];
    const float* f_b     = (const float*)d_in[14];
    float* out = (float*)d_out;

    trunk1_kernel<<<dim3(8, 17), 256>>>(indices, maps, fc1_w, fc1_b);
    trunk2_kernel<<<NMAPS, 512>>>(fc2_w, fc2_b, fc3_w, fc3_b, bn_w, bn_b);
    theta_kernel<<<dim3((ALL_PAIRS + 127) / 128, 8), 128>>>(e_w, e_b, f_w, f_b);
    hyper_kernel<<<dim3(NMAPS, CAP / 32), 512>>>(states, out);
}

// round 15
// speedup vs baseline: 1.5208x; 1.0246x over previous
#include <cuda_runtime.h>
#include <cuda_bf16.h>

// ----------------------------------------------------------------------------
// rlf_53446573032131: hypernetwork (R14 = R9 + 2-samples/thread f-phase)
//   Anchor: R9 (78.3us). R10 (16 outputs/warp) spilled: regs 64, 2.3x issue
//   slots. R12 (packed->f32 smem alone) regressed. This round keeps R9's
//   register shape everywhere except f1/f2, which process TWO sample columns
//   per thread so each uniform weight LDG.128 feeds 2x the FFMA2s. h2 results
//   go straight to a dedicated smem region (no live h2[16] -> no R10 spill).
//   CTA = (map, 64 samples); e-phase = R9's acc[4] code looped over 2 groups.
// ----------------------------------------------------------------------------

#define NMAPS 64
#define BSZ   8192
#define CAP   512

// theta_e (in=2, sz=[64,64,16]):
//   W1@0 [2][64] | b1@128 | W2@192 [64][64] | b2@4288 | W3@4352 [64][16] | b3@5376
// theta_f (in=32, sz=[128,128,8]):
//   W1@0 [32][128] | b1@4096 | W2@4224 [128][128] | b2@20608 | W3@20736 [128][8] | b3@21760
#define TE_SZ 5456
#define TF_SZ 21768
#define TE_PAIRS (TE_SZ / 2)
#define TF_PAIRS (TF_SZ / 2)
#define ALL_PAIRS (TE_PAIRS + TF_PAIRS)

#define HYPER_SMEM (18432 * 4)    // 72 KB dynamic: X 32K | Y 32K | sZ 8K

__device__ int   g_count[NMAPS] = {0};
__device__ int   g_cnt_snap[NMAPS];
__device__ int   g_list[NMAPS * CAP];
__device__ __align__(16) float g_a1[NMAPS * 256];
__device__ __align__(16) float g_z[NMAPS * 32];
__device__ __align__(16) float g_te[NMAPS * TE_SZ];
__device__ __align__(16) float g_tf[NMAPS * TF_SZ];

typedef unsigned long long u64;

__device__ __forceinline__ float leaky(float x) { return fmaxf(x, 0.2f * x); }

// ---- packed f32x2 helpers ----
__device__ __forceinline__ void ffma2(u64& d, u64 a, u64 b) {
    asm("fma.rn.f32x2 %0, %1, %2, %0;" : "+l"(d) : "l"(a), "l"(b));
}
__device__ __forceinline__ u64 add2(u64 a, u64 b) {
    u64 d; asm("add.rn.f32x2 %0, %1, %2;" : "=l"(d) : "l"(a), "l"(b)); return d;
}
__device__ __forceinline__ u64 pack2(float x) {
    u64 r; asm("mov.b64 %0, {%1, %1};" : "=l"(r) : "f"(x)); return r;
}
__device__ __forceinline__ float2 unpack2(u64 v) {
    float2 r; asm("mov.b64 {%0, %1}, %2;" : "=f"(r.x), "=f"(r.y) : "l"(v)); return r;
}

// ------------------------------------------------- trunk L1 + build_lists --
__global__ __launch_bounds__(256) void trunk1_kernel(
    const int*   __restrict__ indices,
    const float* __restrict__ maps,
    const float* __restrict__ fc1_w, const float* __restrict__ fc1_b)
{
    int ot = blockIdx.x, mg = blockIdx.y;
    int tid = threadIdx.x;

    if (mg == 16) {                       // ---- build lists (8 blocks) ----
        int t = ot * 256 + tid;
        #pragma unroll
        for (int s = t; s < BSZ; s += 2048) {
            int m = indices[s];
            int pos = atomicAdd(&g_count[m], 1);
            if (pos < CAP) g_list[m * CAP + pos] = s;
        }
        return;
    }

    __shared__ float ms[4 * 1024];
    __shared__ float red[8 * 32 * 4];

    for (int i = tid; i < 4096; i += 256) ms[i] = maps[mg * 4096 + i];
    __syncthreads();

    int ol = tid & 31, part = tid >> 5;
    int o = ot * 32 + ol;
    float a0 = 0.f, a1 = 0.f, a2 = 0.f, a3 = 0.f;
    int i0 = part * 128;
    #pragma unroll 4
    for (int i = i0; i < i0 + 128; i++) {
        float w = fc1_w[i * 256 + o];
        a0 += ms[i] * w;
        a1 += ms[1024 + i] * w;
        a2 += ms[2048 + i] * w;
        a3 += ms[3072 + i] * w;
    }
    *(float4*)(red + (part * 32 + ol) * 4) = make_float4(a0, a1, a2, a3);
    __syncthreads();

    if (tid < 128) {
        int o2 = tid >> 2, mm = tid & 3;
        float s = fc1_b[ot * 32 + o2];
        #pragma unroll
        for (int p = 0; p < 8; p++) s += red[p * 128 + tid];
        g_a1[(mg * 4 + mm) * 256 + ot * 32 + o2] = leaky(s);
    }
}

// --------------------------------------------- trunk L2-L4 + count snapshot --
__global__ __launch_bounds__(512) void trunk2_kernel(
    const float* __restrict__ fc2_w, const float* __restrict__ fc2_b,
    const float* __restrict__ fc3_w, const float* __restrict__ fc3_b,
    const float* __restrict__ bn_w,  const float* __restrict__ bn_b)
{
    int m = blockIdx.x, tid = threadIdx.x;
    __shared__ float a1[256];
    __shared__ float red[512];
    __shared__ float a2[128];
    __shared__ float a3[128];

    if (tid == 0) {
        int c = g_count[m];
        g_cnt_snap[m] = (c > CAP) ? CAP : c;
        g_count[m] = 0;
    }

    if (tid < 256) a1[tid] = g_a1[m * 256 + tid];
    __syncthreads();

    {   // L2: 256 -> 128
        int o = tid & 127, p = tid >> 7;
        float c0 = 0.f, c1 = 0.f, c2 = 0.f, c3 = 0.f;
        int i0 = p * 64;
        #pragma unroll
        for (int i = i0; i < i0 + 64; i += 4) {
            c0 += a1[i + 0] * fc2_w[(i + 0) * 128 + o];
            c1 += a1[i + 1] * fc2_w[(i + 1) * 128 + o];
            c2 += a1[i + 2] * fc2_w[(i + 2) * 128 + o];
            c3 += a1[i + 3] * fc2_w[(i + 3) * 128 + o];
        }
        red[p * 128 + o] = c0 + c1 + c2 + c3;
    }
    __syncthreads();
    if (tid < 128)
        a2[tid] = leaky(red[tid] + red[128 + tid] + red[256 + tid]
                        + red[384 + tid] + fc2_b[tid]);
    __syncthreads();

    {   // L3: 128 -> 128
        int o = tid & 127, p = tid >> 7;
        float c0 = 0.f, c1 = 0.f, c2 = 0.f, c3 = 0.f;
        int i0 = p * 32;
        #pragma unroll
        for (int i = i0; i < i0 + 32; i += 4) {
            c0 += a2[i + 0] * fc3_w[(i + 0) * 128 + o];
            c1 += a2[i + 1] * fc3_w[(i + 1) * 128 + o];
            c2 += a2[i + 2] * fc3_w[(i + 2) * 128 + o];
            c3 += a2[i + 3] * fc3_w[(i + 3) * 128 + o];
        }
        red[p * 128 + o] = c0 + c1 + c2 + c3;
    }
    __syncthreads();
    if (tid < 128)
        a3[tid] = leaky(red[tid] + red[128 + tid] + red[256 + tid]
                        + red[384 + tid] + fc3_b[tid]);
    __syncthreads();

    {   // L4 (bn): 128 -> 32
        int o = tid & 31, p = tid >> 5;
        float c = 0.f;
        #pragma unroll
        for (int i = p * 8; i < p * 8 + 8; i++)
            c += a3[i] * bn_w[i * 32 + o];
        red[p * 32 + o] = c;
    }
    __syncthreads();
    if (tid < 32) {
        float s = bn_b[tid];
        #pragma unroll
        for (int p = 0; p < 16; p++) s += red[p * 32 + tid];
        g_z[m * 32 + tid] = s;
    }
}

// ------------------------------------------------------------------- theta --
__global__ __launch_bounds__(128) void theta_kernel(
    const float* __restrict__ e_w, const float* __restrict__ e_b,
    const float* __restrict__ f_w, const float* __restrict__ f_b)
{
    __shared__ u64 szp[8 * 32];
    int tid = threadIdx.x;
    int m0 = blockIdx.y * 8;
    for (int i = tid; i < 8 * 32; i += 128) szp[i] = pack2(g_z[m0 * 32 + i]);
    __syncthreads();

    int jp = blockIdx.x * 128 + tid;
    const float* W; const float* Bv; float* dst; int ncol; int j;
    if (jp < TE_PAIRS) { W = e_w; Bv = e_b; dst = g_te; ncol = TE_SZ; j = 2 * jp; }
    else {
        int t = jp - TE_PAIRS;
        if (t >= TF_PAIRS) return;
        W = f_w; Bv = f_b; dst = g_tf; ncol = TF_SZ; j = 2 * t;
    }

    u64 w[32];
    #pragma unroll
    for (int k = 0; k < 32; k++) w[k] = *(const u64*)(W + k * ncol + j);
    u64 bb = *(const u64*)(Bv + j);

    #pragma unroll
    for (int mm = 0; mm < 8; mm++) {
        const ulonglong2* zp = (const ulonglong2*)(szp + mm * 32);
        u64 a0 = bb, a1 = 0, a2 = 0, a3 = 0;
        #pragma unroll
        for (int kk = 0; kk < 16; kk += 2) {
            ulonglong2 za = zp[kk], zb = zp[kk + 1];
            ffma2(a0, za.x, w[2 * kk + 0]); ffma2(a1, za.y, w[2 * kk + 1]);
            ffma2(a2, zb.x, w[2 * kk + 2]); ffma2(a3, zb.y, w[2 * kk + 3]);
        }
        *(u64*)(dst + (m0 + mm) * ncol + j) = add2(add2(a0, a1), add2(a2, a3));
    }
}

// -------------------------------------------------------------------- main --
// CTA = (map, 64 samples), 512 threads / 16 warps, 72KB dynamic smem.
// e-phase (R9 shape, acc[4]): looped over 2 sample-groups of 32.
//   warp w: stream st=w>>3, outputs jh=(w&7)*8; cols = 64-wide (S|G).
// f-phase: 2 samples/thread (cols lane, lane+32), acc[8]:
//   f1: 32->128 read sZ[32][64] -> sF=X [128][64]
//   f2: 128->128 read sF -> h2s=Y [128][64] (separate region, no barrier
//       needed between f2-read and h2-write)
//   f3: warp w -> angle w&7, sample-half w>>3; 128-dot from h2s.
__global__ __launch_bounds__(512) void hyper_kernel(
    const float* __restrict__ states, float* __restrict__ out)
{
    extern __shared__ float SMF[];
    float* X   = SMF;           // sE [64][64] @0 | sB @4096 ; later sF [128][64]
    float* Y   = SMF + 8192;    // h2s [128][64]
    float* sZ  = SMF + 16384;   // zf  [32][64]

    int m = blockIdx.x;
    int cnt = g_cnt_snap[m];
    int base = blockIdx.y * 64;
    if (base >= cnt) return;

    int tid  = threadIdx.x;
    int lane = tid & 31;
    int w    = tid >> 5;        // 0..15
    int st   = w >> 3;          // e-stream: 0 = S, 1 = G
    int wq   = w & 7;

    const float* te = g_te + m * TE_SZ;
    const float* tf = g_tf + m * TF_SZ;

    float* sE = X;
    float* sB = X + 4096;
    float* sF = X;

    int col = lane + st * 32;
    int jh  = wq * 8;

    // ================= e-phase: two groups of 32 samples =================
    #pragma unroll 1
    for (int g = 0; g < 2; g++) {
        int sidx = base + g * 32 + lane;
        int b = g_list[m * CAP + (sidx < cnt ? sidx : base)];
        float2 xv = *(const float2*)(states + 4 * b + st * 2);

        // ---- e1: 2 -> 64 (leaky) ----
        #pragma unroll
        for (int j0 = 0; j0 < 8; j0 += 4) {
            int j = jh + j0;
            float4 w0 = *(const float4*)(te + j);
            float4 w1 = *(const float4*)(te + 64 + j);
            float4 bb = *(const float4*)(te + 128 + j);
            sE[(j + 0) * 64 + col] = leaky(fmaf(xv.x, w0.x, fmaf(xv.y, w1.x, bb.x)));
            sE[(j + 1) * 64 + col] = leaky(fmaf(xv.x, w0.y, fmaf(xv.y, w1.y, bb.y)));
            sE[(j + 2) * 64 + col] = leaky(fmaf(xv.x, w0.z, fmaf(xv.y, w1.z, bb.z)));
            sE[(j + 3) * 64 + col] = leaky(fmaf(xv.x, w0.w, fmaf(xv.y, w1.w, bb.w)));
        }
        __syncthreads();

        // ---- e2: 64 -> 64 (leaky), sE -> sB, 8 outputs/warp, acc[4] ----
        {
            u64 acc[4];
            {
                const ulonglong2* bp = (const ulonglong2*)(te + 4288 + jh);
                ulonglong2 v0 = bp[0], v1 = bp[1];
                acc[0] = v0.x; acc[1] = v0.y; acc[2] = v1.x; acc[3] = v1.y;
            }
            #pragma unroll 4
            for (int k = 0; k < 64; k++) {
                u64 hh = pack2(sE[k * 64 + col]);
                const ulonglong2* wp = (const ulonglong2*)(te + 192 + k * 64 + jh);
                ulonglong2 w0 = wp[0], w1 = wp[1];
                ffma2(acc[0], hh, w0.x); ffma2(acc[1], hh, w0.y);
                ffma2(acc[2], hh, w1.x); ffma2(acc[3], hh, w1.y);
            }
            #pragma unroll
            for (int t = 0; t < 4; t++) {
                float2 r = unpack2(acc[t]);
                sB[(jh + 2*t + 0) * 64 + col] = leaky(r.x);
                sB[(jh + 2*t + 1) * 64 + col] = leaky(r.y);
            }
        }
        __syncthreads();

        // ---- e3: 64 -> 16 (no act), sB -> sZ[32][64], 2 outputs/warp ----
        {
            int j = wq * 2;
            u64 a0 = *(const u64*)(te + 5376 + j);
            u64 a1 = 0;
            #pragma unroll 8
            for (int k = 0; k < 64; k += 2) {
                u64 h0 = pack2(sB[k * 64 + col]);
                u64 h1 = pack2(sB[(k + 1) * 64 + col]);
                u64 w0 = *(const u64*)(te + 4352 + k * 16 + j);
                u64 w1 = *(const u64*)(te + 4352 + (k + 1) * 16 + j);
                ffma2(a0, h0, w0); ffma2(a1, h1, w1);
            }
            float2 r = unpack2(add2(a0, a1));
            int f = j + st * 16;     // e_s -> zf[0:16], e_g -> zf[16:32]
            sZ[(f + 0) * 64 + g * 32 + lane] = r.x;
            sZ[(f + 1) * 64 + g * 32 + lane] = r.y;
        }
        __syncthreads();
    }

    // ================= f-phase: 2 samples per thread =================
    int jf = w * 8;

    // ---- f1: 32 -> 128 (leaky), sZ -> sF [128][64], acc[8] ----
    {
        u64 acc[8];
        {
            const ulonglong2* bp = (const ulonglong2*)(tf + 4096 + jf);
            ulonglong2 v0 = bp[0], v1 = bp[1];
            acc[0] = v0.x; acc[1] = v0.y; acc[2] = v1.x; acc[3] = v1.y;
            acc[4] = v0.x; acc[5] = v0.y; acc[6] = v1.x; acc[7] = v1.y;
        }
        #pragma unroll 2
        for (int k = 0; k < 32; k++) {
            u64 h0 = pack2(sZ[k * 64 + lane]);
            u64 h1 = pack2(sZ[k * 64 + 32 + lane]);
            const ulonglong2* wp = (const ulonglong2*)(tf + k * 128 + jf);
            ulonglong2 w0 = wp[0], w1 = wp[1];
            ffma2(acc[0], h0, w0.x); ffma2(acc[1], h0, w0.y);
            ffma2(acc[2], h0, w1.x); ffma2(acc[3], h0, w1.y);
            ffma2(acc[4], h1, w0.x); ffma2(acc[5], h1, w0.y);
            ffma2(acc[6], h1, w1.x); ffma2(acc[7], h1, w1.y);
        }
        // sF overlays sE/sB; last e-reads ended at the loop-end barrier.
        #pragma unroll
        for (int t = 0; t < 4; t++) {
            float2 r0 = unpack2(acc[t]);
            float2 r1 = unpack2(acc[4 + t]);
            sF[(jf + 2*t + 0) * 64 + lane]      = leaky(r0.x);
            sF[(jf + 2*t + 1) * 64 + lane]      = leaky(r0.y);
            sF[(jf + 2*t + 0) * 64 + 32 + lane] = leaky(r1.x);
            sF[(jf + 2*t + 1) * 64 + 32 + lane] = leaky(r1.y);
        }
    }
    __syncthreads();

    // ---- f2: 128 -> 128 (leaky), sF -> h2s (Y), acc[8] ----
    {
        u64 acc[8];
        {
            const ulonglong2* bp = (const ulonglong2*)(tf + 20608 + jf);
            ulonglong2 v0 = bp[0], v1 = bp[1];
            acc[0] = v0.x; acc[1] = v0.y; acc[2] = v1.x; acc[3] = v1.y;
            acc[4] = v0.x; acc[5] = v0.y; acc[6] = v1.x; acc[7] = v1.y;
        }
        #pragma unroll 2
        for (int k = 0; k < 128; k++) {
            u64 h0 = pack2(sF[k * 64 + lane]);
            u64 h1 = pack2(sF[k * 64 + 32 + lane]);
            const ulonglong2* wp = (const ulonglong2*)(tf + 4224 + k * 128 + jf);
            ulonglong2 w0 = wp[0], w1 = wp[1];
            ffma2(acc[0], h0, w0.x); ffma2(acc[1], h0, w0.y);
            ffma2(acc[2], h0, w1.x); ffma2(acc[3], h0, w1.y);
            ffma2(acc[4], h1, w0.x); ffma2(acc[5], h1, w0.y);
            ffma2(acc[6], h1, w1.x); ffma2(acc[7], h1, w1.y);
        }
        // h2s is a DIFFERENT smem region (Y): safe to write while other warps
        // still read sF (X). One barrier after suffices.
        float* h2s = Y;
        #pragma unroll
        for (int t = 0; t < 4; t++) {
            float2 r0 = unpack2(acc[t]);
            float2 r1 = unpack2(acc[4 + t]);
            h2s[(jf + 2*t + 0) * 64 + lane]      = leaky(r0.x);
            h2s[(jf + 2*t + 1) * 64 + lane]      = leaky(r0.y);
            h2s[(jf + 2*t + 0) * 64 + 32 + lane] = leaky(r1.x);
            h2s[(jf + 2*t + 1) * 64 + 32 + lane] = leaky(r1.y);
        }
    }
    __syncthreads();

    // ---- f3: 128 -> 8; warp w -> angle r=w&7, sample-half w>>3 ----
    {
        int r    = w & 7;
        int half = w >> 3;
        int fcol = half * 32 + lane;
        int sidx2 = base + half * 32 + lane;
        if (sidx2 < cnt) {
            int b2 = g_list[m * CAP + sidx2];
            const float* h2s = Y;
            float s = tf[21760 + r];
            #pragma unroll 8
            for (int j = 0; j < 128; j++)
                s = fmaf(h2s[j * 64 + fcol], tf[20736 + j * 8 + r], s);
            out[b2 * 16 + r]     = __sinf(s);
            out[b2 * 16 + 8 + r] = __cosf(s);
        }
    }
}

// ----------------------------------------------------------------- launch --
extern "C" void kernel_launch(void* const* d_in, const int* in_sizes, int n_in,
                              void* d_out, int out_size)
{
    const int*   indices = (const int*)  d_in[0];
    const float* states  = (const float*)d_in[1];
    const float* maps    = (const float*)d_in[2];
    const float* fc1_w   = (const float*)d_in[3];
    const float* fc1_b   = (const float*)d_in[4];
    const float* fc2_w   = (const float*)d_in[5];
    const float* fc2_b   = (const float*)d_in[6];
    const float* fc3_w   = (const float*)d_in[7];
    const float* fc3_b   = (const float*)d_in[8];
    const float* bn_w    = (const float*)d_in[9];
    const float* bn_b    = (const float*)d_in[10];
    const float* e_w     = (const float*)d_in[11];
    const float* e_b     = (const float*)d_in[12];
    const float* f_w     = (const float*)d_in[13];
    const float* f_b     = (const float*)d_in[14];
    float* out = (float*)d_out;

    cudaFuncSetAttribute(hyper_kernel,
                         cudaFuncAttributeMaxDynamicSharedMemorySize, HYPER_SMEM);

    trunk1_kernel<<<dim3(8, 17), 256>>>(indices, maps, fc1_w, fc1_b);
    trunk2_kernel<<<NMAPS, 512>>>(fc2_w, fc2_b, fc3_w, fc3_b, bn_w, bn_b);
    theta_kernel<<<dim3((ALL_PAIRS + 127) / 128, 8), 128>>>(e_w, e_b, f_w, f_b);
    hyper_kernel<<<dim3(NMAPS, CAP / 64), 512, HYPER_SMEM>>>(states, out);
}

// round 17
// speedup vs baseline: 2.3234x; 1.5277x over previous
#include <cuda_runtime.h>
#include <cuda_bf16.h>

// ----------------------------------------------------------------------------
// rlf_53446573032131: hypernetwork (R16 = R15 resubmit; infra failed, untested)
//   R9 (78.3us) is the anchor; R10/R12/R14 all regressed by deviating from
//   its shape. Single change here: each hyper CTA stages its map's f2 weight
//   block (tf[4224..20608), 64KB) into DYNAMIC smem with a coalesced float4
//   copy, so the hottest loop's uniform weight loads become LDS (29cyc) not
//   L2 LDG (~250cyc). Everything else is byte-identical to R9.
// ----------------------------------------------------------------------------

#define NMAPS 64
#define BSZ   8192
#define CAP   512

// theta_e (in=2, sz=[64,64,16]):
//   W1@0 [2][64] | b1@128 | W2@192 [64][64] | b2@4288 | W3@4352 [64][16] | b3@5376
// theta_f (in=32, sz=[128,128,8]):
//   W1@0 [32][128] | b1@4096 | W2@4224 [128][128] | b2@20608 | W3@20736 [128][8] | b3@21760
#define TE_SZ 5456
#define TF_SZ 21768
#define TE_PAIRS (TE_SZ / 2)
#define TF_PAIRS (TF_SZ / 2)
#define ALL_PAIRS (TE_PAIRS + TF_PAIRS)

#define W2_SMEM (16384 * 4)     // 64 KB dynamic: f2 weight block

__device__ int   g_count[NMAPS] = {0};
__device__ int   g_cnt_snap[NMAPS];
__device__ int   g_list[NMAPS * CAP];
__device__ __align__(16) float g_a1[NMAPS * 256];
__device__ __align__(16) float g_z[NMAPS * 32];
__device__ __align__(16) float g_te[NMAPS * TE_SZ];
__device__ __align__(16) float g_tf[NMAPS * TF_SZ];

typedef unsigned long long u64;

__device__ __forceinline__ float leaky(float x) { return fmaxf(x, 0.2f * x); }

// ---- packed f32x2 helpers ----
__device__ __forceinline__ void ffma2(u64& d, u64 a, u64 b) {
    asm("fma.rn.f32x2 %0, %1, %2, %0;" : "+l"(d) : "l"(a), "l"(b));
}
__device__ __forceinline__ u64 add2(u64 a, u64 b) {
    u64 d; asm("add.rn.f32x2 %0, %1, %2;" : "=l"(d) : "l"(a), "l"(b)); return d;
}
__device__ __forceinline__ u64 pack2(float x) {
    u64 r; asm("mov.b64 %0, {%1, %1};" : "=l"(r) : "f"(x)); return r;
}
__device__ __forceinline__ float2 unpack2(u64 v) {
    float2 r; asm("mov.b64 {%0, %1}, %2;" : "=f"(r.x), "=f"(r.y) : "l"(v)); return r;
}

// ------------------------------------------------- trunk L1 + build_lists --
__global__ __launch_bounds__(256) void trunk1_kernel(
    const int*   __restrict__ indices,
    const float* __restrict__ maps,
    const float* __restrict__ fc1_w, const float* __restrict__ fc1_b)
{
    int ot = blockIdx.x, mg = blockIdx.y;
    int tid = threadIdx.x;

    if (mg == 16) {                       // ---- build lists (8 blocks) ----
        int t = ot * 256 + tid;
        #pragma unroll
        for (int s = t; s < BSZ; s += 2048) {
            int m = indices[s];
            int pos = atomicAdd(&g_count[m], 1);
            if (pos < CAP) g_list[m * CAP + pos] = s;
        }
        return;
    }

    __shared__ float ms[4 * 1024];
    __shared__ float red[8 * 32 * 4];

    for (int i = tid; i < 4096; i += 256) ms[i] = maps[mg * 4096 + i];
    __syncthreads();

    int ol = tid & 31, part = tid >> 5;
    int o = ot * 32 + ol;
    float a0 = 0.f, a1 = 0.f, a2 = 0.f, a3 = 0.f;
    int i0 = part * 128;
    #pragma unroll 4
    for (int i = i0; i < i0 + 128; i++) {
        float w = fc1_w[i * 256 + o];
        a0 += ms[i] * w;
        a1 += ms[1024 + i] * w;
        a2 += ms[2048 + i] * w;
        a3 += ms[3072 + i] * w;
    }
    *(float4*)(red + (part * 32 + ol) * 4) = make_float4(a0, a1, a2, a3);
    __syncthreads();

    if (tid < 128) {
        int o2 = tid >> 2, mm = tid & 3;
        float s = fc1_b[ot * 32 + o2];
        #pragma unroll
        for (int p = 0; p < 8; p++) s += red[p * 128 + tid];
        g_a1[(mg * 4 + mm) * 256 + ot * 32 + o2] = leaky(s);
    }
}

// --------------------------------------------- trunk L2-L4 + count snapshot --
__global__ __launch_bounds__(512) void trunk2_kernel(
    const float* __restrict__ fc2_w, const float* __restrict__ fc2_b,
    const float* __restrict__ fc3_w, const float* __restrict__ fc3_b,
    const float* __restrict__ bn_w,  const float* __restrict__ bn_b)
{
    int m = blockIdx.x, tid = threadIdx.x;
    __shared__ float a1[256];
    __shared__ float red[512];
    __shared__ float a2[128];
    __shared__ float a3[128];

    if (tid == 0) {
        int c = g_count[m];
        g_cnt_snap[m] = (c > CAP) ? CAP : c;
        g_count[m] = 0;
    }

    if (tid < 256) a1[tid] = g_a1[m * 256 + tid];
    __syncthreads();

    {   // L2: 256 -> 128
        int o = tid & 127, p = tid >> 7;
        float c0 = 0.f, c1 = 0.f, c2 = 0.f, c3 = 0.f;
        int i0 = p * 64;
        #pragma unroll
        for (int i = i0; i < i0 + 64; i += 4) {
            c0 += a1[i + 0] * fc2_w[(i + 0) * 128 + o];
            c1 += a1[i + 1] * fc2_w[(i + 1) * 128 + o];
            c2 += a1[i + 2] * fc2_w[(i + 2) * 128 + o];
            c3 += a1[i + 3] * fc2_w[(i + 3) * 128 + o];
        }
        red[p * 128 + o] = c0 + c1 + c2 + c3;
    }
    __syncthreads();
    if (tid < 128)
        a2[tid] = leaky(red[tid] + red[128 + tid] + red[256 + tid]
                        + red[384 + tid] + fc2_b[tid]);
    __syncthreads();

    {   // L3: 128 -> 128
        int o = tid & 127, p = tid >> 7;
        float c0 = 0.f, c1 = 0.f, c2 = 0.f, c3 = 0.f;
        int i0 = p * 32;
        #pragma unroll
        for (int i = i0; i < i0 + 32; i += 4) {
            c0 += a2[i + 0] * fc3_w[(i + 0) * 128 + o];
            c1 += a2[i + 1] * fc3_w[(i + 1) * 128 + o];
            c2 += a2[i + 2] * fc3_w[(i + 2) * 128 + o];
            c3 += a2[i + 3] * fc3_w[(i + 3) * 128 + o];
        }
        red[p * 128 + o] = c0 + c1 + c2 + c3;
    }
    __syncthreads();
    if (tid < 128)
        a3[tid] = leaky(red[tid] + red[128 + tid] + red[256 + tid]
                        + red[384 + tid] + fc3_b[tid]);
    __syncthreads();

    {   // L4 (bn): 128 -> 32
        int o = tid & 31, p = tid >> 5;
        float c = 0.f;
        #pragma unroll
        for (int i = p * 8; i < p * 8 + 8; i++)
            c += a3[i] * bn_w[i * 32 + o];
        red[p * 32 + o] = c;
    }
    __syncthreads();
    if (tid < 32) {
        float s = bn_b[tid];
        #pragma unroll
        for (int p = 0; p < 16; p++) s += red[p * 32 + tid];
        g_z[m * 32 + tid] = s;
    }
}

// ------------------------------------------------------------------- theta --
__global__ __launch_bounds__(128) void theta_kernel(
    const float* __restrict__ e_w, const float* __restrict__ e_b,
    const float* __restrict__ f_w, const float* __restrict__ f_b)
{
    __shared__ u64 szp[8 * 32];
    int tid = threadIdx.x;
    int m0 = blockIdx.y * 8;
    for (int i = tid; i < 8 * 32; i += 128) szp[i] = pack2(g_z[m0 * 32 + i]);
    __syncthreads();

    int jp = blockIdx.x * 128 + tid;
    const float* W; const float* Bv; float* dst; int ncol; int j;
    if (jp < TE_PAIRS) { W = e_w; Bv = e_b; dst = g_te; ncol = TE_SZ; j = 2 * jp; }
    else {
        int t = jp - TE_PAIRS;
        if (t >= TF_PAIRS) return;
        W = f_w; Bv = f_b; dst = g_tf; ncol = TF_SZ; j = 2 * t;
    }

    u64 w[32];
    #pragma unroll
    for (int k = 0; k < 32; k++) w[k] = *(const u64*)(W + k * ncol + j);
    u64 bb = *(const u64*)(Bv + j);

    #pragma unroll
    for (int mm = 0; mm < 8; mm++) {
        const ulonglong2* zp = (const ulonglong2*)(szp + mm * 32);
        u64 a0 = bb, a1 = 0, a2 = 0, a3 = 0;
        #pragma unroll
        for (int kk = 0; kk < 16; kk += 2) {
            ulonglong2 za = zp[kk], zb = zp[kk + 1];
            ffma2(a0, za.x, w[2 * kk + 0]); ffma2(a1, za.y, w[2 * kk + 1]);
            ffma2(a2, zb.x, w[2 * kk + 2]); ffma2(a3, zb.y, w[2 * kk + 3]);
        }
        *(u64*)(dst + (m0 + mm) * ncol + j) = add2(add2(a0, a1), add2(a2, a3));
    }
}

// -------------------------------------------------------------------- main --
// R9 hyper verbatim (CTA = map x 32 samples, 512 thr / 16 warps, acc[4],
// packed f-phase smem) + ONE change: f2's 64KB weight block is staged into
// dynamic smem (W2s) by a coalesced float4 copy at kernel start, and the f2
// inner loop reads weights via uniform LDS.128 instead of L2 LDG.
// smem: static X 32KB + Zp 8KB; dynamic W2s 64KB. 104KB/CTA -> 2 CTAs/SM
// (active CTAs are only ~1.9/SM, so no occupancy loss).
__global__ __launch_bounds__(512) void hyper_kernel(
    const float* __restrict__ states, float* __restrict__ out)
{
    extern __shared__ __align__(16) float W2s[];   // [128][128] f2 weights

    int m = blockIdx.x;
    int cnt = g_cnt_snap[m];
    int base = blockIdx.y * 32;
    if (base >= cnt) return;

    int tid  = threadIdx.x;
    int lane = tid & 31;
    int w    = tid >> 5;        // 0..15
    int st   = w >> 3;          // e-stream: 0 = S, 1 = G
    int wq   = w & 7;           // warp-in-stream
    int sidx = base + lane;
    bool valid = sidx < cnt;
    int b = g_list[m * CAP + (valid ? sidx : base)];

    const float* te = g_te + m * TE_SZ;
    const float* tf = g_tf + m * TF_SZ;

    __shared__ __align__(16) u64 X[4096];    // 32KB multi-purpose
    __shared__ __align__(16) u64 Zp[1024];   // zf packed [32][32]

    float* sE  = (float*)X;          // [64][64] e1 out
    float* sB  = ((float*)X) + 4096; // [64][64] e2 out
    u64*   sFp = X;                  // [128][32] f1 out (packed)
    float* h2s = (float*)X;          // [128][32] f2 out

    // ---- stage f2 weights (tf[4224..20608)) into smem, coalesced ----
    {
        const float4* src = (const float4*)(tf + 4224);
        float4* dst = (float4*)W2s;
        #pragma unroll
        for (int i = 0; i < 8; i++)
            dst[tid + i * 512] = src[tid + i * 512];
    }

    int col = lane + st * 32;
    float2 xv = *(const float2*)(states + 4 * b + st * 2);
    int jh = wq * 8;

    // ---- e1: 2 -> 64 (leaky) ----
    #pragma unroll
    for (int j0 = 0; j0 < 8; j0 += 4) {
        int j = jh + j0;
        float4 w0 = *(const float4*)(te + j);
        float4 w1 = *(const float4*)(te + 64 + j);
        float4 bb = *(const float4*)(te + 128 + j);
        sE[(j + 0) * 64 + col] = leaky(fmaf(xv.x, w0.x, fmaf(xv.y, w1.x, bb.x)));
        sE[(j + 1) * 64 + col] = leaky(fmaf(xv.x, w0.y, fmaf(xv.y, w1.y, bb.y)));
        sE[(j + 2) * 64 + col] = leaky(fmaf(xv.x, w0.z, fmaf(xv.y, w1.z, bb.z)));
        sE[(j + 3) * 64 + col] = leaky(fmaf(xv.x, w0.w, fmaf(xv.y, w1.w, bb.w)));
    }
    __syncthreads();   // covers e1 writes AND the W2s copy

    // ---- e2: 64 -> 64 (leaky), sE -> sB, 8 outputs/warp ----
    {
        u64 acc[4];
        {
            const ulonglong2* bp = (const ulonglong2*)(te + 4288 + jh);
            ulonglong2 v0 = bp[0], v1 = bp[1];
            acc[0] = v0.x; acc[1] = v0.y; acc[2] = v1.x; acc[3] = v1.y;
        }
        #pragma unroll 4
        for (int k = 0; k < 64; k++) {
            u64 hh = pack2(sE[k * 64 + col]);
            const ulonglong2* wp = (const ulonglong2*)(te + 192 + k * 64 + jh);
            ulonglong2 w0 = wp[0], w1 = wp[1];
            ffma2(acc[0], hh, w0.x); ffma2(acc[1], hh, w0.y);
            ffma2(acc[2], hh, w1.x); ffma2(acc[3], hh, w1.y);
        }
        #pragma unroll
        for (int t = 0; t < 4; t++) {
            float2 r = unpack2(acc[t]);
            sB[(jh + 2*t + 0) * 64 + col] = leaky(r.x);
            sB[(jh + 2*t + 1) * 64 + col] = leaky(r.y);
        }
    }
    __syncthreads();

    // ---- e3: 64 -> 16 (no act), sB -> Zp (packed), 2 outputs/warp ----
    {
        int j = wq * 2;
        u64 a0 = *(const u64*)(te + 5376 + j);
        u64 a1 = 0;
        #pragma unroll 8
        for (int k = 0; k < 64; k += 2) {
            u64 h0 = pack2(sB[k * 64 + col]);
            u64 h1 = pack2(sB[(k + 1) * 64 + col]);
            u64 w0 = *(const u64*)(te + 4352 + k * 16 + j);
            u64 w1 = *(const u64*)(te + 4352 + (k + 1) * 16 + j);
            ffma2(a0, h0, w0); ffma2(a1, h1, w1);
        }
        float2 r = unpack2(add2(a0, a1));
        int f = j + st * 16;     // e_s -> zf[0:16], e_g -> zf[16:32]
        Zp[(f + 0) * 32 + lane] = pack2(r.x);
        Zp[(f + 1) * 32 + lane] = pack2(r.y);
    }
    __syncthreads();

    // ---- f1: 32 -> 128 (leaky), Zp -> sFp (packed), 8 outputs/warp ----
    int jf = w * 8;
    {
        u64 acc[4];
        {
            const ulonglong2* bp = (const ulonglong2*)(tf + 4096 + jf);
            ulonglong2 v0 = bp[0], v1 = bp[1];
            acc[0] = v0.x; acc[1] = v0.y; acc[2] = v1.x; acc[3] = v1.y;
        }
        #pragma unroll 4
        for (int k = 0; k < 32; k++) {
            u64 hh = Zp[k * 32 + lane];
            const ulonglong2* wp = (const ulonglong2*)(tf + k * 128 + jf);
            ulonglong2 w0 = wp[0], w1 = wp[1];
            ffma2(acc[0], hh, w0.x); ffma2(acc[1], hh, w0.y);
            ffma2(acc[2], hh, w1.x); ffma2(acc[3], hh, w1.y);
        }
        // sFp overlays sE/sB; last e-reads ended at the previous barrier.
        #pragma unroll
        for (int t = 0; t < 4; t++) {
            float2 r = unpack2(acc[t]);
            sFp[(jf + 2*t + 0) * 32 + lane] = pack2(leaky(r.x));
            sFp[(jf + 2*t + 1) * 32 + lane] = pack2(leaky(r.y));
        }
    }
    __syncthreads();

    // ---- f2: 128 -> 128 (leaky), weights from smem W2s, h2 in regs ----
    float h2[8];
    {
        u64 acc[4];
        {
            const ulonglong2* bp = (const ulonglong2*)(tf + 20608 + jf);
            ulonglong2 v0 = bp[0], v1 = bp[1];
            acc[0] = v0.x; acc[1] = v0.y; acc[2] = v1.x; acc[3] = v1.y;
        }
        #pragma unroll 4
        for (int k = 0; k < 128; k++) {
            u64 hh = sFp[k * 32 + lane];
            const ulonglong2* wp = (const ulonglong2*)(W2s + k * 128 + jf);
            ulonglong2 w0 = wp[0], w1 = wp[1];
            ffma2(acc[0], hh, w0.x); ffma2(acc[1], hh, w0.y);
            ffma2(acc[2], hh, w1.x); ffma2(acc[3], hh, w1.y);
        }
        #pragma unroll
        for (int t = 0; t < 4; t++) {
            float2 r = unpack2(acc[t]);
            h2[2*t]     = leaky(r.x);
            h2[2*t + 1] = leaky(r.y);
        }
    }
    __syncthreads();            // everyone done READING sFp
    #pragma unroll
    for (int t = 0; t < 8; t++) h2s[(jf + t) * 32 + lane] = h2[t];
    __syncthreads();

    // ---- f3: 128 -> 8, warp r (<8) computes angle r; sin/cos epilogue ----
    if (w < 8 && valid) {
        int r = w;
        float s = tf[21760 + r];
        #pragma unroll 8
        for (int j = 0; j < 128; j++)
            s = fmaf(h2s[j * 32 + lane], tf[20736 + j * 8 + r], s);
        out[b * 16 + r]     = __sinf(s);
        out[b * 16 + 8 + r] = __cosf(s);
    }
}

// ----------------------------------------------------------------- launch --
extern "C" void kernel_launch(void* const* d_in, const int* in_sizes, int n_in,
                              void* d_out, int out_size)
{
    const int*   indices = (const int*)  d_in[0];
    const float* states  = (const float*)d_in[1];
    const float* maps    = (const float*)d_in[2];
    const float* fc1_w   = (const float*)d_in[3];
    const float* fc1_b   = (const float*)d_in[4];
    const float* fc2_w   = (const float*)d_in[5];
    const float* fc2_b   = (const float*)d_in[6];
    const float* fc3_w   = (const float*)d_in[7];
    const float* fc3_b   = (const float*)d_in[8];
    const float* bn_w    = (const float*)d_in[9];
    const float* bn_b    = (const float*)d_in[10];
    const float* e_w     = (const float*)d_in[11];
    const float* e_b     = (const float*)d_in[12];
    const float* f_w     = (const float*)d_in[13];
    const float* f_b     = (const float*)d_in[14];
    float* out = (float*)d_out;

    cudaFuncSetAttribute(hyper_kernel,
                         cudaFuncAttributeMaxDynamicSharedMemorySize, W2_SMEM);

    trunk1_kernel<<<dim3(8, 17), 256>>>(indices, maps, fc1_w, fc1_b);
    trunk2_kernel<<<NMAPS, 512>>>(fc2_w, fc2_b, fc3_w, fc3_b, bn_w, bn_b);
    theta_kernel<<<dim3((ALL_PAIRS + 127) / 128, 8), 128>>>(e_w, e_b, f_w, f_b);
    hyper_kernel<<<dim3(NMAPS, CAP / 32), 512, W2_SMEM>>>(states, out);
}